// round 6
// baseline (speedup 1.0000x reference)
#include <cuda_runtime.h>

// YOLO v1 loss: pred/target (2048,14,14,30) fp32 -> scalar fp32.
// Single-kernel: coalesced float4 staging with on-the-fly channel split
// (boxes kept raw, class channels stored as diffs -> 40 floats/cell smem),
// per-cell loss, deterministic fixed-point atomic fan-in.

#define TPB 128
#define CH  30
#define SCALE_BITS 24

__device__ unsigned long long g_acc = 0ULL;
__device__ unsigned int g_done = 0u;

__global__ void __launch_bounds__(TPB, 10) yolo_fused_kernel(
    const float* __restrict__ pred,
    const float* __restrict__ tgt,
    float* __restrict__ out,
    int cells, float invN)
{
    __shared__ float sp[TPB * 10];   // pred ch 0..9   (5120 B)
    __shared__ float st[TPB * 10];   // tgt  ch 0..9   (5120 B)
    __shared__ float sd[TPB * 20];   // pred-tgt ch 10..29 (10240 B)

    const int tid = threadIdx.x;
    const long long base = (long long)blockIdx.x * (TPB * CH);
    const int cell0 = blockIdx.x * TPB;

    // Coalesced staging with channel routing. 960 float4s per tensor.
    {
        const float4* p4 = reinterpret_cast<const float4*>(pred + base);
        const float4* t4 = reinterpret_cast<const float4*>(tgt + base);
        #pragma unroll
        for (int i = tid; i < (TPB * CH) / 4; i += TPB) {
            float4 pv = p4[i];
            float4 tv = t4[i];
            int g = 4 * i;
            #pragma unroll
            for (int e = 0; e < 4; e++) {
                float pe = (&pv.x)[e];
                float te = (&tv.x)[e];
                int gg = g + e;
                int cell = gg / 30;          // magic-mul, no real div
                int c = gg - cell * 30;
                if (c < 10) {
                    sp[cell * 10 + c] = pe;
                    st[cell * 10 + c] = te;
                } else {
                    sd[cell * 20 + (c - 10)] = pe - te;
                }
            }
        }
    }
    __syncthreads();

    float v = 0.0f;
    if (cell0 + tid < cells) {
        const float* p = sp + tid * 10;
        const float* t = st + tid * 10;
        const float* d = sd + tid * 20;
        const float inv14 = 1.0f / 14.0f;

        float conf_t = t[4];
        float coo = (conf_t > 0.0f) ? 1.0f : 0.0f;
        float noo = (conf_t == 0.0f) ? 1.0f : 0.0f;

        // no-object confidence loss (both boxes)
        float d4 = p[4] - t[4];
        float d9 = p[9] - t[9];
        float noo_loss = d4 * d4 + d9 * d9;

        // class loss (diffs already staged)
        float cls = 0.0f;
        #pragma unroll
        for (int c = 0; c < 20; c++)
            cls += d[c] * d[c];

        // target box 0 -> xyxy
        float t0x1 = t[0] * inv14 - 0.5f * t[2];
        float t0y1 = t[1] * inv14 - 0.5f * t[3];
        float t0x2 = t[0] * inv14 + 0.5f * t[2];
        float t0y2 = t[1] * inv14 + 0.5f * t[3];
        float a2 = (t0x2 - t0x1) * (t0y2 - t0y1);

        float iou[2];
        #pragma unroll
        for (int b = 0; b < 2; b++) {
            const float* bb = p + 5 * b;
            float x1 = bb[0] * inv14 - 0.5f * bb[2];
            float y1 = bb[1] * inv14 - 0.5f * bb[3];
            float x2 = bb[0] * inv14 + 0.5f * bb[2];
            float y2 = bb[1] * inv14 + 0.5f * bb[3];
            float lx = fmaxf(x1, t0x1);
            float ly = fmaxf(y1, t0y1);
            float rx = fminf(x2, t0x2);
            float ry = fminf(y2, t0y2);
            float w = fmaxf(rx - lx, 0.0f);
            float h = fmaxf(ry - ly, 0.0f);
            float inter = w * h;
            float a1 = (x2 - x1) * (y2 - y1);
            iou[b] = inter / (a1 + a2 - inter);
        }

        // argmax with first-max tie-break (jnp.argmax semantics)
        int idx = (iou[1] > iou[0]) ? 1 : 0;
        float max_iou = fmaxf(iou[0], iou[1]);

        const float* pr = p + 5 * idx;
        const float* tr = t + 5 * idx;

        float dconf = pr[4] - max_iou;
        float contain = dconf * dconf;

        float dx = pr[0] - tr[0];
        float dy = pr[1] - tr[1];
        float dw = sqrtf(pr[2]) - sqrtf(tr[2]);
        float dh = sqrtf(pr[3]) - sqrtf(tr[3]);
        float loc = dx * dx + dy * dy + dw * dw + dh * dh;

        float oconf = idx ? p[4] : p[9];   // non-responsible box confidence
        float not_contain = oconf * oconf;

        v = coo * (5.0f * loc + 2.0f * contain + not_contain + cls)
          + 0.5f * noo * noo_loss;
    }

    // warp reduce (float)
    #pragma unroll
    for (int o = 16; o > 0; o >>= 1)
        v += __shfl_down_sync(0xffffffffu, v, o);

    __shared__ float warpsum[TPB / 32];
    if ((tid & 31) == 0) warpsum[tid >> 5] = v;
    __syncthreads();

    if (tid == 0) {
        double s = 0.0;
        #pragma unroll
        for (int i = 0; i < TPB / 32; i++) s += (double)warpsum[i];

        // fixed-point contribution (all loss terms are >= 0)
        unsigned long long q =
            (unsigned long long)__double2ll_rn(s * (double)(1 << SCALE_BITS));
        atomicAdd(&g_acc, q);
        __threadfence();

        unsigned int ticket = atomicAdd(&g_done, 1u);
        if (ticket == gridDim.x - 1) {
            unsigned long long tot = atomicAdd(&g_acc, 0ULL);
            out[0] = (float)((double)tot *
                             (1.0 / (double)(1 << SCALE_BITS)) * (double)invN);
            // reset for next graph replay
            g_acc = 0ULL;
            g_done = 0u;
        }
    }
}

extern "C" void kernel_launch(void* const* d_in, const int* in_sizes, int n_in,
                              void* d_out, int out_size)
{
    const float* pred = (const float*)d_in[0];
    const float* tgt  = (const float*)d_in[1];
    float* out = (float*)d_out;

    int total = in_sizes[0];           // 2048*14*14*30
    int cells = total / CH;            // 401408
    int N = cells / (14 * 14);         // 2048
    int blocks = (cells + TPB - 1) / TPB;  // 3136

    yolo_fused_kernel<<<blocks, TPB>>>(pred, tgt, out, cells, 1.0f / (float)N);
}

// round 7
// speedup vs baseline: 1.4366x; 1.4366x over previous
#include <cuda_runtime.h>
#include <cstdint>

// YOLO v1 loss: pred/target (2048,14,14,30) fp32 -> scalar fp32.
// Staging via cp.async.bulk (TMA path, one issuing thread per block) into
// smem, per-cell loss compute, deterministic fixed-point atomic fan-in.

#define TPB 128
#define CH  30
#define TILE_BYTES (TPB * CH * 4)   // 15360
#define SCALE_BITS 24

__device__ unsigned long long g_acc = 0ULL;
__device__ unsigned int g_done = 0u;

__device__ __forceinline__ uint32_t smem_u32(const void* p) {
    uint32_t a;
    asm("{ .reg .u64 t; cvta.to.shared.u64 t, %1; cvt.u32.u64 %0, t; }"
        : "=r"(a) : "l"(p));
    return a;
}

__global__ void __launch_bounds__(TPB) yolo_fused_kernel(
    const float* __restrict__ pred,
    const float* __restrict__ tgt,
    float* __restrict__ out,
    int cells, float invN)
{
    __shared__ float sp[TPB * CH];            // 15360 B
    __shared__ float st[TPB * CH];            // 15360 B
    __shared__ alignas(8) unsigned long long mbar;

    const int tid = threadIdx.x;
    const long long base = (long long)blockIdx.x * (TPB * CH);

    const uint32_t mbar_a = smem_u32(&mbar);

    if (tid == 0) {
        asm volatile("mbarrier.init.shared.b64 [%0], %1;"
                     :: "r"(mbar_a), "r"(1) : "memory");
    }
    __syncthreads();   // mbar init visible to all threads (and async proxy)

    if (tid == 0) {
        asm volatile("mbarrier.arrive.expect_tx.shared.b64 _, [%0], %1;"
                     :: "r"(mbar_a), "r"(2 * TILE_BYTES) : "memory");
        uint32_t sp_a = smem_u32(sp);
        uint32_t st_a = smem_u32(st);
        asm volatile(
            "cp.async.bulk.shared::cta.global.mbarrier::complete_tx::bytes "
            "[%0], [%1], %2, [%3];"
            :: "r"(sp_a), "l"(pred + base), "r"((uint32_t)TILE_BYTES), "r"(mbar_a)
            : "memory");
        asm volatile(
            "cp.async.bulk.shared::cta.global.mbarrier::complete_tx::bytes "
            "[%0], [%1], %2, [%3];"
            :: "r"(st_a), "l"(tgt + base), "r"((uint32_t)TILE_BYTES), "r"(mbar_a)
            : "memory");
    }

    // Wait for both bulk copies (phase 0).
    {
        uint32_t done;
        asm volatile(
            "{\n\t"
            ".reg .pred p;\n\t"
            "mbarrier.try_wait.parity.acquire.cta.shared::cta.b64 p, [%1], 0;\n\t"
            "selp.b32 %0, 1, 0, p;\n\t"
            "}"
            : "=r"(done) : "r"(mbar_a) : "memory");
        if (!done) {
            asm volatile(
                "{\n\t"
                ".reg .pred P1;\n\t"
                "W_%=:\n\t"
                "mbarrier.try_wait.parity.acquire.cta.shared::cta.b64 P1, [%0], 0, 0x989680;\n\t"
                "@P1 bra.uni D_%=;\n\t"
                "bra.uni W_%=;\n\t"
                "D_%=:\n\t"
                "}"
                :: "r"(mbar_a) : "memory");
        }
    }

    float v;
    {
        const float* p = sp + tid * CH;
        const float* t = st + tid * CH;
        const float inv14 = 1.0f / 14.0f;

        float conf_t = t[4];
        float coo = (conf_t > 0.0f) ? 1.0f : 0.0f;
        float noo = (conf_t == 0.0f) ? 1.0f : 0.0f;

        // no-object confidence loss (both boxes)
        float d4 = p[4] - t[4];
        float d9 = p[9] - t[9];
        float noo_loss = d4 * d4 + d9 * d9;

        // class loss (channels 10..29)
        float cls = 0.0f;
        #pragma unroll
        for (int c = 10; c < 30; c++) {
            float dc = p[c] - t[c];
            cls += dc * dc;
        }

        // target box 0 -> xyxy
        float t0x1 = t[0] * inv14 - 0.5f * t[2];
        float t0y1 = t[1] * inv14 - 0.5f * t[3];
        float t0x2 = t[0] * inv14 + 0.5f * t[2];
        float t0y2 = t[1] * inv14 + 0.5f * t[3];
        float a2 = (t0x2 - t0x1) * (t0y2 - t0y1);

        float iou[2];
        #pragma unroll
        for (int b = 0; b < 2; b++) {
            const float* bb = p + 5 * b;
            float x1 = bb[0] * inv14 - 0.5f * bb[2];
            float y1 = bb[1] * inv14 - 0.5f * bb[3];
            float x2 = bb[0] * inv14 + 0.5f * bb[2];
            float y2 = bb[1] * inv14 + 0.5f * bb[3];
            float lx = fmaxf(x1, t0x1);
            float ly = fmaxf(y1, t0y1);
            float rx = fminf(x2, t0x2);
            float ry = fminf(y2, t0y2);
            float w = fmaxf(rx - lx, 0.0f);
            float h = fmaxf(ry - ly, 0.0f);
            float inter = w * h;
            float a1 = (x2 - x1) * (y2 - y1);
            iou[b] = inter / (a1 + a2 - inter);
        }

        // argmax with first-max tie-break (jnp.argmax semantics)
        int idx = (iou[1] > iou[0]) ? 1 : 0;
        float max_iou = fmaxf(iou[0], iou[1]);

        const float* pr = p + 5 * idx;
        const float* tr = t + 5 * idx;

        float dconf = pr[4] - max_iou;
        float contain = dconf * dconf;

        float dx = pr[0] - tr[0];
        float dy = pr[1] - tr[1];
        float dw = sqrtf(pr[2]) - sqrtf(tr[2]);
        float dh = sqrtf(pr[3]) - sqrtf(tr[3]);
        float loc = dx * dx + dy * dy + dw * dw + dh * dh;

        float oconf = idx ? p[4] : p[9];   // non-responsible box confidence
        float not_contain = oconf * oconf;

        v = coo * (5.0f * loc + 2.0f * contain + not_contain + cls)
          + 0.5f * noo * noo_loss;
    }

    // warp reduce (float)
    #pragma unroll
    for (int o = 16; o > 0; o >>= 1)
        v += __shfl_down_sync(0xffffffffu, v, o);

    __shared__ float warpsum[TPB / 32];
    if ((tid & 31) == 0) warpsum[tid >> 5] = v;
    __syncthreads();

    if (tid == 0) {
        double s = 0.0;
        #pragma unroll
        for (int i = 0; i < TPB / 32; i++) s += (double)warpsum[i];

        // fixed-point contribution (all loss terms are >= 0)
        unsigned long long q =
            (unsigned long long)__double2ll_rn(s * (double)(1 << SCALE_BITS));
        atomicAdd(&g_acc, q);
        __threadfence();

        unsigned int ticket = atomicAdd(&g_done, 1u);
        if (ticket == gridDim.x - 1) {
            unsigned long long tot = atomicAdd(&g_acc, 0ULL);
            out[0] = (float)((double)tot *
                             (1.0 / (double)(1 << SCALE_BITS)) * (double)invN);
            // reset for next graph replay
            g_acc = 0ULL;
            g_done = 0u;
        }
    }
}

extern "C" void kernel_launch(void* const* d_in, const int* in_sizes, int n_in,
                              void* d_out, int out_size)
{
    const float* pred = (const float*)d_in[0];
    const float* tgt  = (const float*)d_in[1];
    float* out = (float*)d_out;

    int total = in_sizes[0];           // 2048*14*14*30
    int cells = total / CH;            // 401408  (= 3136 * 128 exactly)
    int N = cells / (14 * 14);         // 2048
    int blocks = cells / TPB;          // 3136

    yolo_fused_kernel<<<blocks, TPB>>>(pred, tgt, out, cells, 1.0f / (float)N);
}